// round 8
// baseline (speedup 1.0000x reference)
#include <cuda_runtime.h>
#include <cstddef>

#define NTOK 256
#define NHID 2048
#define NEXP 64
#define NINT 1408
#define KSEL 6

// ---------------- scratch (__device__ globals; no allocation) ----------------
__device__ int   g_cnt[NEXP];
__device__ int   g_tok[NEXP * NTOK];
__device__ int   g_slot[NEXP * NTOK];
__device__ float g_wgt[NEXP * NTOK];
__device__ int   g_tki[NTOK * KSEL];
__device__ float g_tkw[NTOK * KSEL];
__device__ float g_h[(size_t)NTOK * KSEL * NINT];
__device__ float g_part[(size_t)NTOK * KSEL * NHID];

// ---------------- router: one block per token, one thread per expert ----------------
__global__ void k_router(const float* x, const float* gw) {
    __shared__ float logits[NEXP];
    const int t = blockIdx.x;
    const int e = threadIdx.x;          // 0..63
    const float* xr = x + (size_t)t * NHID;
    float acc = 0.0f;
    for (int h = 0; h < NHID; h++)
        acc += xr[h] * gw[(size_t)h * NEXP + e];   // coalesced across e
    logits[e] = acc;
    __syncthreads();

    if (e == 0) {
        // top-6 by logit (softmax is monotone; its denominator cancels in the
        // renormalization). Strict > keeps the lowest index on ties (lax.top_k).
        int   chosen[KSEL];
        float lval[KSEL];
        unsigned long long used = 0ULL;
        for (int k = 0; k < KSEL; k++) {
            float best = -1e30f; int bi = 0;
            for (int j = 0; j < NEXP; j++) {
                if (((used >> j) & 1ULL) == 0ULL && logits[j] > best) { best = logits[j]; bi = j; }
            }
            used |= (1ULL << bi);
            chosen[k] = bi;
            lval[k]   = best;
        }
        const float mx = lval[0];
        float w[KSEL];
        float s = 0.0f;
        for (int k = 0; k < KSEL; k++) { w[k] = __expf(lval[k] - mx); s += w[k]; }
        const float inv = 1.0f / s;
        for (int k = 0; k < KSEL; k++) {
            g_tki[t * KSEL + k] = chosen[k];
            g_tkw[t * KSEL + k] = w[k] * inv;
        }
    }
}

// ---------------- deterministic expert-list build ----------------
__global__ void k_build() {
    const int e = blockIdx.x;
    if (threadIdx.x != 0) return;
    int cnt = 0;
    for (int t = 0; t < NTOK; t++) {
        for (int k = 0; k < KSEL; k++) {
            if (g_tki[t * KSEL + k] == e) {
                g_tok[e * NTOK + cnt]  = t;
                g_slot[e * NTOK + cnt] = t * KSEL + k;
                g_wgt[e * NTOK + cnt]  = g_tkw[t * KSEL + k];
                cnt++;
            }
        }
    }
    g_cnt[e] = cnt;
}

// ---------------- GEMM1: g_h[slot] = silu(x[tok] @ w1[e]) ----------------
// Tile: 32 gathered rows x 128 cols, K-chunks of 32. 256 threads, 4x4 per thread.
// All loads/stores scalar.
__global__ void __launch_bounds__(256) k_gemm1(const float* w1, const float* x) {
    const int e  = blockIdx.x;
    const int n0 = blockIdx.y * 128;
    const int ne = g_cnt[e];
    if (ne == 0) return;

    __shared__ float xs[32][32];
    __shared__ float ws[32][128];

    const int tid = threadIdx.x;
    const int mg  = tid >> 5;        // 0..7, uniform per warp (A broadcast)
    const int ng  = tid & 31;        // 0..31

    for (int m0 = 0; m0 < ne; m0 += 32) {
        float acc[4][4];
        for (int i = 0; i < 4; i++)
            for (int j = 0; j < 4; j++) acc[i][j] = 0.0f;

        for (int k0 = 0; k0 < NHID; k0 += 32) {
            // stage A (zero-pad invalid rows)
            for (int j = tid; j < 32 * 32; j += 256) {
                const int r = j >> 5, c = j & 31;
                const int row = m0 + r;
                float v = 0.0f;
                if (row < ne) {
                    const int tok = g_tok[e * NTOK + row];
                    v = x[(size_t)tok * NHID + k0 + c];
                }
                xs[r][c] = v;
            }
            // stage W1 chunk: rows k0..k0+31, cols n0..n0+127
            for (int j = tid; j < 32 * 128; j += 256) {
                const int kk = j >> 7, nn = j & 127;
                ws[kk][nn] = w1[((size_t)e * NHID + k0 + kk) * NINT + n0 + nn];
            }
            __syncthreads();

            for (int k = 0; k < 32; k++) {
                const float b0 = ws[k][ng * 4 + 0];
                const float b1 = ws[k][ng * 4 + 1];
                const float b2 = ws[k][ng * 4 + 2];
                const float b3 = ws[k][ng * 4 + 3];
                for (int i = 0; i < 4; i++) {
                    const float a = xs[mg * 4 + i][k];
                    acc[i][0] = fmaf(a, b0, acc[i][0]);
                    acc[i][1] = fmaf(a, b1, acc[i][1]);
                    acc[i][2] = fmaf(a, b2, acc[i][2]);
                    acc[i][3] = fmaf(a, b3, acc[i][3]);
                }
            }
            __syncthreads();
        }

        for (int i = 0; i < 4; i++) {
            const int row = m0 + mg * 4 + i;
            if (row < ne) {
                const int sl = g_slot[e * NTOK + row];
                for (int j = 0; j < 4; j++) {
                    const float v = acc[i][j];
                    const float sv = v / (1.0f + __expf(-v));   // silu
                    g_h[(size_t)sl * NINT + n0 + ng * 4 + j] = sv;
                }
            }
        }
    }
}

// ---------------- GEMM2: g_part[slot] = wgt * (g_h[slot] @ w2[e]) ----------------
__global__ void __launch_bounds__(256) k_gemm2(const float* w2) {
    const int e  = blockIdx.x;
    const int n0 = blockIdx.y * 128;
    const int ne = g_cnt[e];
    if (ne == 0) return;

    __shared__ float xs[32][32];
    __shared__ float ws[32][128];

    const int tid = threadIdx.x;
    const int mg  = tid >> 5;
    const int ng  = tid & 31;

    for (int m0 = 0; m0 < ne; m0 += 32) {
        float acc[4][4];
        for (int i = 0; i < 4; i++)
            for (int j = 0; j < 4; j++) acc[i][j] = 0.0f;

        for (int k0 = 0; k0 < NINT; k0 += 32) {
            for (int j = tid; j < 32 * 32; j += 256) {
                const int r = j >> 5, c = j & 31;
                const int row = m0 + r;
                float v = 0.0f;
                if (row < ne) {
                    const int sl = g_slot[e * NTOK + row];
                    v = g_h[(size_t)sl * NINT + k0 + c];
                }
                xs[r][c] = v;
            }
            for (int j = tid; j < 32 * 128; j += 256) {
                const int kk = j >> 7, nn = j & 127;
                ws[kk][nn] = w2[((size_t)e * NINT + k0 + kk) * NHID + n0 + nn];
            }
            __syncthreads();

            for (int k = 0; k < 32; k++) {
                const float b0 = ws[k][ng * 4 + 0];
                const float b1 = ws[k][ng * 4 + 1];
                const float b2 = ws[k][ng * 4 + 2];
                const float b3 = ws[k][ng * 4 + 3];
                for (int i = 0; i < 4; i++) {
                    const float a = xs[mg * 4 + i][k];
                    acc[i][0] = fmaf(a, b0, acc[i][0]);
                    acc[i][1] = fmaf(a, b1, acc[i][1]);
                    acc[i][2] = fmaf(a, b2, acc[i][2]);
                    acc[i][3] = fmaf(a, b3, acc[i][3]);
                }
            }
            __syncthreads();
        }

        for (int i = 0; i < 4; i++) {
            const int row = m0 + mg * 4 + i;
            if (row < ne) {
                const int sl = g_slot[e * NTOK + row];
                const float sc = g_wgt[e * NTOK + row];
                for (int j = 0; j < 4; j++)
                    g_part[(size_t)sl * NHID + n0 + ng * 4 + j] = acc[i][j] * sc;
            }
        }
    }
}

// ---------------- combine: out[t][h] = sum over 6 slots ----------------
__global__ void k_combine(float* out) {
    const int i = blockIdx.x * 256 + threadIdx.x;
    if (i >= NTOK * NHID) return;
    const int t  = i / NHID;
    const int hh = i - t * NHID;
    float s = 0.0f;
    for (int k = 0; k < KSEL; k++)
        s += g_part[(size_t)(t * KSEL + k) * NHID + hh];
    out[i] = s;
}

// ---------------- launch ----------------
extern "C" void kernel_launch(void* const* d_in, const int* in_sizes, int n_in,
                              void* d_out, int out_size) {
    if (n_in < 4) return;

    // Ordinal binding, order- and unit-independent:
    // two largest buffers = w1, w2 (original order preserved on ties),
    // next largest = x, next = gate_w. topk input unused (KSEL compile-time).
    int used[16];
    for (int i = 0; i < 16; i++) used[i] = 0;
    const int m = (n_in < 16) ? n_in : 16;
    int ord[4];
    for (int r = 0; r < 4; r++) {
        int b = -1;
        for (int i = 0; i < m; i++) {
            if (!used[i] && (b < 0 || (long long)in_sizes[i] > (long long)in_sizes[b])) b = i;
        }
        if (b < 0) return;
        used[b] = 1;
        ord[r] = b;
    }
    const float* w1 = (const float*)d_in[ord[0]];
    const float* w2 = (const float*)d_in[ord[1]];
    const float* x  = (const float*)d_in[ord[2]];
    const float* gw = (const float*)d_in[ord[3]];
    float* out = (float*)d_out;

    k_router<<<NTOK, NEXP>>>(x, gw);
    k_build<<<NEXP, 32>>>();
    k_gemm1<<<dim3(NEXP, NINT / 128), 256>>>(w1, x);
    k_gemm2<<<dim3(NEXP, NHID / 128), 256>>>(w2);
    k_combine<<<(NTOK * NHID + 255) / 256, 256>>>(out);
}

// round 9
// speedup vs baseline: 1.6190x; 1.6190x over previous
#include <cuda_runtime.h>
#include <cstddef>

#define NTOK 256
#define NHID 2048
#define NEXP 64
#define NINT 1408
#define KSEL 6

// ---------------- scratch (__device__ globals; no allocation) ----------------
__device__ int   g_cnt[NEXP];
__device__ int   g_tok[NEXP * NTOK];
__device__ int   g_slot[NEXP * NTOK];
__device__ float g_wgt[NEXP * NTOK];
__device__ int   g_tki[NTOK * KSEL];
__device__ float g_tkw[NTOK * KSEL];
__device__ __align__(16) float g_h[(size_t)NTOK * KSEL * NINT];
__device__ __align__(16) float g_part[(size_t)NTOK * KSEL * NHID];

// ---------------- packed f32x2 helpers ----------------
static __device__ __forceinline__ unsigned long long pk2(float lo, float hi) {
    unsigned long long r;
    asm("mov.b64 %0, {%1, %2};" : "=l"(r) : "f"(lo), "f"(hi));
    return r;
}
static __device__ __forceinline__ void upk2(unsigned long long v, float& lo, float& hi) {
    asm("mov.b64 {%0, %1}, %2;" : "=f"(lo), "=f"(hi) : "l"(v));
}
static __device__ __forceinline__ void ffma2(unsigned long long& d,
                                             unsigned long long a,
                                             unsigned long long b) {
    asm("fma.rn.f32x2 %0, %1, %2, %0;" : "+l"(d) : "l"(a), "l"(b));
}

// ---------------- router: one block per token, 256 threads (4-way K split) ----------------
__global__ void k_router(const float* x, const float* gw) {
    __shared__ float xrow[NHID];
    __shared__ float part[4][NEXP];
    __shared__ float logits[NEXP];

    const int t = blockIdx.x;
    for (int i = threadIdx.x; i < NHID; i += 256) xrow[i] = x[(size_t)t * NHID + i];
    __syncthreads();

    const int e   = threadIdx.x & 63;
    const int seg = threadIdx.x >> 6;        // 4 segments of 512
    const int k0  = seg * 512;
    float a0 = 0.f, a1 = 0.f, a2 = 0.f, a3 = 0.f;
    for (int h = k0; h < k0 + 512; h += 4) {
        a0 += xrow[h + 0] * gw[(size_t)(h + 0) * NEXP + e];
        a1 += xrow[h + 1] * gw[(size_t)(h + 1) * NEXP + e];
        a2 += xrow[h + 2] * gw[(size_t)(h + 2) * NEXP + e];
        a3 += xrow[h + 3] * gw[(size_t)(h + 3) * NEXP + e];
    }
    part[seg][e] = (a0 + a1) + (a2 + a3);
    __syncthreads();
    if (threadIdx.x < NEXP)
        logits[threadIdx.x] = part[0][threadIdx.x] + part[1][threadIdx.x] +
                              part[2][threadIdx.x] + part[3][threadIdx.x];
    __syncthreads();

    if (threadIdx.x == 0) {
        // top-6 by logit (softmax monotone; denominator cancels in renorm).
        // Strict > keeps lowest index on ties (lax.top_k order).
        int   chosen[KSEL];
        float lval[KSEL];
        unsigned long long used = 0ULL;
        for (int k = 0; k < KSEL; k++) {
            float best = -1e30f; int bi = 0;
            for (int j = 0; j < NEXP; j++)
                if (((used >> j) & 1ULL) == 0ULL && logits[j] > best) { best = logits[j]; bi = j; }
            used |= (1ULL << bi);
            chosen[k] = bi;
            lval[k]   = best;
        }
        const float mx = lval[0];
        float w[KSEL], s = 0.0f;
        for (int k = 0; k < KSEL; k++) { w[k] = __expf(lval[k] - mx); s += w[k]; }
        const float inv = 1.0f / s;
        for (int k = 0; k < KSEL; k++) {
            g_tki[t * KSEL + k] = chosen[k];
            g_tkw[t * KSEL + k] = w[k] * inv;
        }
    }
}

// ---------------- deterministic expert-list build ----------------
__global__ void k_build() {
    const int e = blockIdx.x;
    if (threadIdx.x != 0) return;
    int cnt = 0;
    for (int t = 0; t < NTOK; t++)
        for (int k = 0; k < KSEL; k++)
            if (g_tki[t * KSEL + k] == e) {
                g_tok[e * NTOK + cnt]  = t;
                g_slot[e * NTOK + cnt] = t * KSEL + k;
                g_wgt[e * NTOK + cnt]  = g_tkw[t * KSEL + k];
                cnt++;
            }
    g_cnt[e] = cnt;
}

// ---------------- GEMM1: g_h[slot] = silu(x[tok] @ w1[e]) ----------------
// Tile 32(M) x 128(N), K-chunks of 32, 256 threads, 4x4 per thread as f32x2 pairs.
__global__ void __launch_bounds__(256) k_gemm1(const float* w1, const float* x) {
    const int e  = blockIdx.x;
    const int n0 = blockIdx.y * 128;
    const int ne = g_cnt[e];
    if (ne == 0) return;

    __shared__ float4 xs4[32][8];     // A tile 32x32
    __shared__ float4 ws4[32][32];    // W tile 32x128

    const float* xsf = (const float*)xs4;

    const int tid = threadIdx.x;
    const int mg  = tid >> 5;         // 0..7, uniform per warp (A broadcast)
    const int ng  = tid & 31;         // 0..31
    const int sr  = tid >> 3;         // A stage row
    const int sc  = tid & 7;          // A stage col (float4)

    for (int m0 = 0; m0 < ne; m0 += 32) {
        unsigned long long acc[4][2];
        for (int i = 0; i < 4; i++) { acc[i][0] = 0ULL; acc[i][1] = 0ULL; }

        const int arow = m0 + sr;
        const float* asrc = (arow < ne) ? (x + (size_t)g_tok[e * NTOK + arow] * NHID) : 0;

        for (int k0 = 0; k0 < NHID; k0 += 32) {
            float4 av = make_float4(0.f, 0.f, 0.f, 0.f);
            if (asrc) av = *(const float4*)(asrc + k0 + sc * 4);
            xs4[sr][sc] = av;

            #pragma unroll
            for (int r = 0; r < 4; r++) {
                const int i4 = tid + r * 256;          // float4 index in 32x32
                const int kk = i4 >> 5;
                const int nn = i4 & 31;
                ws4[kk][nn] = *(const float4*)(w1 + ((size_t)e * NHID + k0 + kk) * NINT + n0 + nn * 4);
            }
            __syncthreads();

            #pragma unroll 8
            for (int k = 0; k < 32; k++) {
                const ulonglong2 bb = *(const ulonglong2*)&ws4[k][ng];
                #pragma unroll
                for (int i = 0; i < 4; i++) {
                    const float a = xsf[(mg * 4 + i) * 32 + k];   // warp broadcast
                    const unsigned long long ad = pk2(a, a);
                    ffma2(acc[i][0], ad, bb.x);
                    ffma2(acc[i][1], ad, bb.y);
                }
            }
            __syncthreads();
        }

        #pragma unroll
        for (int i = 0; i < 4; i++) {
            const int row = m0 + mg * 4 + i;
            if (row < ne) {
                const int sl = g_slot[e * NTOK + row];
                float o[4];
                upk2(acc[i][0], o[0], o[1]);
                upk2(acc[i][1], o[2], o[3]);
                #pragma unroll
                for (int j = 0; j < 4; j++)
                    o[j] = o[j] / (1.0f + __expf(-o[j]));        // silu
                *(float4*)(g_h + (size_t)sl * NINT + n0 + ng * 4) = make_float4(o[0], o[1], o[2], o[3]);
            }
        }
    }
}

// ---------------- GEMM2: g_part[slot] = wgt * (g_h[slot] @ w2[e]) ----------------
__global__ void __launch_bounds__(256) k_gemm2(const float* w2) {
    const int e  = blockIdx.x;
    const int n0 = blockIdx.y * 128;
    const int ne = g_cnt[e];
    if (ne == 0) return;

    __shared__ float4 xs4[32][8];
    __shared__ float4 ws4[32][32];

    const float* xsf = (const float*)xs4;

    const int tid = threadIdx.x;
    const int mg  = tid >> 5;
    const int ng  = tid & 31;
    const int sr  = tid >> 3;
    const int sc  = tid & 7;

    for (int m0 = 0; m0 < ne; m0 += 32) {
        unsigned long long acc[4][2];
        for (int i = 0; i < 4; i++) { acc[i][0] = 0ULL; acc[i][1] = 0ULL; }

        const int arow = m0 + sr;
        const float* asrc = (arow < ne) ? (g_h + (size_t)g_slot[e * NTOK + arow] * NINT) : 0;

        for (int k0 = 0; k0 < NINT; k0 += 32) {
            float4 av = make_float4(0.f, 0.f, 0.f, 0.f);
            if (asrc) av = *(const float4*)(asrc + k0 + sc * 4);
            xs4[sr][sc] = av;

            #pragma unroll
            for (int r = 0; r < 4; r++) {
                const int i4 = tid + r * 256;
                const int kk = i4 >> 5;
                const int nn = i4 & 31;
                ws4[kk][nn] = *(const float4*)(w2 + ((size_t)e * NINT + k0 + kk) * NHID + n0 + nn * 4);
            }
            __syncthreads();

            #pragma unroll 8
            for (int k = 0; k < 32; k++) {
                const ulonglong2 bb = *(const ulonglong2*)&ws4[k][ng];
                #pragma unroll
                for (int i = 0; i < 4; i++) {
                    const float a = xsf[(mg * 4 + i) * 32 + k];
                    const unsigned long long ad = pk2(a, a);
                    ffma2(acc[i][0], ad, bb.x);
                    ffma2(acc[i][1], ad, bb.y);
                }
            }
            __syncthreads();
        }

        #pragma unroll
        for (int i = 0; i < 4; i++) {
            const int row = m0 + mg * 4 + i;
            if (row < ne) {
                const int sl = g_slot[e * NTOK + row];
                const float sc2 = g_wgt[e * NTOK + row];
                float o[4];
                upk2(acc[i][0], o[0], o[1]);
                upk2(acc[i][1], o[2], o[3]);
                *(float4*)(g_part + (size_t)sl * NHID + n0 + ng * 4) =
                    make_float4(o[0] * sc2, o[1] * sc2, o[2] * sc2, o[3] * sc2);
            }
        }
    }
}

// ---------------- combine: out[t][h] = sum over 6 slots ----------------
__global__ void k_combine(float* out) {
    const int i = blockIdx.x * 256 + threadIdx.x;
    if (i >= NTOK * NHID) return;
    const int t  = i / NHID;
    const int hh = i - t * NHID;
    float s = 0.0f;
    for (int k = 0; k < KSEL; k++)
        s += g_part[(size_t)(t * KSEL + k) * NHID + hh];
    out[i] = s;
}

// ---------------- launch ----------------
extern "C" void kernel_launch(void* const* d_in, const int* in_sizes, int n_in,
                              void* d_out, int out_size) {
    if (n_in < 4) return;

    // Ordinal binding, order- and unit-independent (sizes NEVER interpreted
    // numerically): two largest = w1, w2 (original order on ties), then x, then gate_w.
    int used[16];
    for (int i = 0; i < 16; i++) used[i] = 0;
    const int m = (n_in < 16) ? n_in : 16;
    int ord[4];
    for (int r = 0; r < 4; r++) {
        int b = -1;
        for (int i = 0; i < m; i++)
            if (!used[i] && (b < 0 || (long long)in_sizes[i] > (long long)in_sizes[b])) b = i;
        if (b < 0) return;
        used[b] = 1;
        ord[r] = b;
    }
    const float* w1 = (const float*)d_in[ord[0]];
    const float* w2 = (const float*)d_in[ord[1]];
    const float* x  = (const float*)d_in[ord[2]];
    const float* gw = (const float*)d_in[ord[3]];
    float* out = (float*)d_out;

    k_router<<<NTOK, 256>>>(x, gw);
    k_build<<<NEXP, 32>>>();
    k_gemm1<<<dim3(NEXP, NINT / 128), 256>>>(w1, x);
    k_gemm2<<<dim3(NEXP, NHID / 128), 256>>>(w2);
    k_combine<<<(NTOK * NHID + 255) / 256, 256>>>(out);
}

// round 10
// speedup vs baseline: 1.7824x; 1.1009x over previous
#include <cuda_runtime.h>
#include <cstddef>

#define NTOK 256
#define NHID 2048
#define NEXP 64
#define NINT 1408
#define KSEL 6
#define KC   16

// ---------------- scratch (__device__ globals; no allocation) ----------------
__device__ int   g_cnt[NEXP];
__device__ int   g_tok[NEXP * NTOK];
__device__ int   g_slot[NEXP * NTOK];
__device__ float g_wgt[NEXP * NTOK];
__device__ int   g_tki[NTOK * KSEL];
__device__ float g_tkw[NTOK * KSEL];
__device__ __align__(16) float g_h[(size_t)NTOK * KSEL * NINT];
__device__ __align__(16) float g_part[(size_t)NTOK * KSEL * NHID];

// ---------------- packed f32x2 helpers ----------------
static __device__ __forceinline__ unsigned long long pk2(float lo, float hi) {
    unsigned long long r;
    asm("mov.b64 %0, {%1, %2};" : "=l"(r) : "f"(lo), "f"(hi));
    return r;
}
static __device__ __forceinline__ void upk2(unsigned long long v, float& lo, float& hi) {
    asm("mov.b64 {%0, %1}, %2;" : "=f"(lo), "=f"(hi) : "l"(v));
}
static __device__ __forceinline__ void ffma2(unsigned long long& d,
                                             unsigned long long a,
                                             unsigned long long b) {
    asm("fma.rn.f32x2 %0, %1, %2, %0;" : "+l"(d) : "l"(a), "l"(b));
}

// ---------------- router: one block per token, 256 threads ----------------
__global__ void k_router(const float* x, const float* gw) {
    __shared__ float xrow[NHID];
    __shared__ float part[4][NEXP];
    __shared__ float logits[NEXP];

    const int t = blockIdx.x;
    for (int i = threadIdx.x; i < NHID; i += 256) xrow[i] = x[(size_t)t * NHID + i];
    __syncthreads();

    const int e   = threadIdx.x & 63;
    const int seg = threadIdx.x >> 6;
    const int k0  = seg * 512;
    float a0 = 0.f, a1 = 0.f, a2 = 0.f, a3 = 0.f;
    for (int h = k0; h < k0 + 512; h += 4) {
        a0 += xrow[h + 0] * gw[(size_t)(h + 0) * NEXP + e];
        a1 += xrow[h + 1] * gw[(size_t)(h + 1) * NEXP + e];
        a2 += xrow[h + 2] * gw[(size_t)(h + 2) * NEXP + e];
        a3 += xrow[h + 3] * gw[(size_t)(h + 3) * NEXP + e];
    }
    part[seg][e] = (a0 + a1) + (a2 + a3);
    __syncthreads();
    if (threadIdx.x < NEXP)
        logits[threadIdx.x] = part[0][threadIdx.x] + part[1][threadIdx.x] +
                              part[2][threadIdx.x] + part[3][threadIdx.x];
    __syncthreads();

    if (threadIdx.x == 0) {
        // top-6 by logit (softmax monotone; denominator cancels in renorm).
        // Strict > keeps lowest index on ties (lax.top_k order).
        int   chosen[KSEL];
        float lval[KSEL];
        unsigned long long used = 0ULL;
        for (int k = 0; k < KSEL; k++) {
            float best = -1e30f; int bi = 0;
            for (int j = 0; j < NEXP; j++)
                if (((used >> j) & 1ULL) == 0ULL && logits[j] > best) { best = logits[j]; bi = j; }
            used |= (1ULL << bi);
            chosen[k] = bi;
            lval[k]   = best;
        }
        const float mx = lval[0];
        float w[KSEL], s = 0.0f;
        for (int k = 0; k < KSEL; k++) { w[k] = __expf(lval[k] - mx); s += w[k]; }
        const float inv = 1.0f / s;
        for (int k = 0; k < KSEL; k++) {
            g_tki[t * KSEL + k] = chosen[k];
            g_tkw[t * KSEL + k] = w[k] * inv;
        }
    }
}

// ---------------- parallel deterministic expert-list build ----------------
// Ballot + warp-prefix compaction over slot indices in ascending order:
// result order identical to the old serial scan.
__global__ void k_build() {
    const int e   = blockIdx.x;
    const int tid = threadIdx.x;
    __shared__ int wsum[8];
    __shared__ int base;
    if (tid == 0) base = 0;
    __syncthreads();

    for (int b0 = 0; b0 < NTOK * KSEL; b0 += 256) {
        const int idx = b0 + tid;                       // = t*KSEL + k, ascending
        const bool p  = (g_tki[idx] == e);
        const unsigned mask = __ballot_sync(0xffffffffu, p);
        const int lane = tid & 31;
        const int w    = tid >> 5;
        const int pre  = __popc(mask & ((1u << lane) - 1u));
        if (lane == 31) wsum[w] = __popc(mask);
        __syncthreads();
        int woff = 0;
        for (int j = 0; j < w; j++) woff += wsum[j];
        if (p) {
            const int pos = base + woff + pre;
            g_tok[e * NTOK + pos]  = idx / KSEL;
            g_slot[e * NTOK + pos] = idx;
            g_wgt[e * NTOK + pos]  = g_tkw[idx];
        }
        __syncthreads();
        if (tid == 0) {
            int tot = 0;
            for (int j = 0; j < 8; j++) tot += wsum[j];
            base += tot;
        }
        __syncthreads();
    }
    if (tid == 0) g_cnt[e] = base;
}

// ---------------- GEMM1: g_h[slot] = silu(x[tok] @ w1[e]) ----------------
// 128 threads, M-tile 32 (4 warps x 8 rows), N-tile 128 (32 lanes x 4 cols),
// KC=16 chunks, double-buffered smem, A duplicated as (a,a) pairs in [k][row].
__global__ void __launch_bounds__(128) k_gemm1(const float* w1, const float* x) {
    const int e  = blockIdx.x;
    const int n0 = blockIdx.y * 128;
    const int ne = g_cnt[e];
    if (ne == 0) return;

    __shared__ float4             bs[2][KC][32];   // B: [k][n/4]
    __shared__ unsigned long long as[2][KC][32];   // A dup: [k][row]

    const int tid = threadIdx.x;
    const int ng  = tid & 31;        // col group (4 cols)
    const int mg  = tid >> 5;        // 0..3 -> rows mg*8..mg*8+7
    const int arl = tid & 31;        // A staging row
    const int aks = (tid >> 5) * 4;  // A staging k offset (4 k's)

    for (int m0 = 0; m0 < ne; m0 += 32) {
        unsigned long long acc[8][2];
        #pragma unroll
        for (int i = 0; i < 8; i++) { acc[i][0] = 0ULL; acc[i][1] = 0ULL; }

        const int ar = m0 + arl;
        const float* asrc = (ar < ne) ? (x + (size_t)g_tok[e * NTOK + ar] * NHID) : 0;

        // prologue: stage chunk 0 into buffer 0
        {
            #pragma unroll
            for (int r = 0; r < 4; r++) {
                const int j  = tid + r * 128;
                const int kk = j >> 5, nn = j & 31;
                bs[0][kk][nn] = *(const float4*)(w1 + ((size_t)e * NHID + kk) * NINT + n0 + nn * 4);
            }
            float4 av = make_float4(0.f, 0.f, 0.f, 0.f);
            if (asrc) av = *(const float4*)(asrc + aks);
            as[0][aks + 0][arl] = pk2(av.x, av.x);
            as[0][aks + 1][arl] = pk2(av.y, av.y);
            as[0][aks + 2][arl] = pk2(av.z, av.z);
            as[0][aks + 3][arl] = pk2(av.w, av.w);
        }
        __syncthreads();

        const int nc = NHID / KC;
        for (int c = 0; c < nc; c++) {
            const int cur = c & 1;
            float4 pb0, pb1, pb2, pb3, pa;
            const bool more = (c + 1 < nc);
            if (more) {
                const int kn = (c + 1) * KC;
                {
                    int j = tid;             int kk = j >> 5, nn = j & 31;
                    pb0 = *(const float4*)(w1 + ((size_t)e * NHID + kn + kk) * NINT + n0 + nn * 4);
                }
                {
                    int j = tid + 128;       int kk = j >> 5, nn = j & 31;
                    pb1 = *(const float4*)(w1 + ((size_t)e * NHID + kn + kk) * NINT + n0 + nn * 4);
                }
                {
                    int j = tid + 256;       int kk = j >> 5, nn = j & 31;
                    pb2 = *(const float4*)(w1 + ((size_t)e * NHID + kn + kk) * NINT + n0 + nn * 4);
                }
                {
                    int j = tid + 384;       int kk = j >> 5, nn = j & 31;
                    pb3 = *(const float4*)(w1 + ((size_t)e * NHID + kn + kk) * NINT + n0 + nn * 4);
                }
                pa = make_float4(0.f, 0.f, 0.f, 0.f);
                if (asrc) pa = *(const float4*)(asrc + kn + aks);
            }

            #pragma unroll
            for (int k = 0; k < KC; k++) {
                const ulonglong2 b = *(const ulonglong2*)&bs[cur][k][ng];
                #pragma unroll
                for (int p = 0; p < 4; p++) {
                    const ulonglong2 a2 = *(const ulonglong2*)&as[cur][k][mg * 8 + p * 2];
                    ffma2(acc[p * 2    ][0], a2.x, b.x);
                    ffma2(acc[p * 2    ][1], a2.x, b.y);
                    ffma2(acc[p * 2 + 1][0], a2.y, b.x);
                    ffma2(acc[p * 2 + 1][1], a2.y, b.y);
                }
            }

            if (more) {
                const int nb = cur ^ 1;
                { int j = tid;       bs[nb][j >> 5][j & 31] = pb0; }
                { int j = tid + 128; bs[nb][j >> 5][j & 31] = pb1; }
                { int j = tid + 256; bs[nb][j >> 5][j & 31] = pb2; }
                { int j = tid + 384; bs[nb][j >> 5][j & 31] = pb3; }
                as[nb][aks + 0][arl] = pk2(pa.x, pa.x);
                as[nb][aks + 1][arl] = pk2(pa.y, pa.y);
                as[nb][aks + 2][arl] = pk2(pa.z, pa.z);
                as[nb][aks + 3][arl] = pk2(pa.w, pa.w);
            }
            __syncthreads();
        }

        #pragma unroll
        for (int i = 0; i < 8; i++) {
            const int row = m0 + mg * 8 + i;
            if (row < ne) {
                const int sl = g_slot[e * NTOK + row];
                float o0, o1, o2, o3;
                upk2(acc[i][0], o0, o1);
                upk2(acc[i][1], o2, o3);
                o0 = o0 / (1.0f + __expf(-o0));
                o1 = o1 / (1.0f + __expf(-o1));
                o2 = o2 / (1.0f + __expf(-o2));
                o3 = o3 / (1.0f + __expf(-o3));
                *(float4*)(g_h + (size_t)sl * NINT + n0 + ng * 4) = make_float4(o0, o1, o2, o3);
            }
        }
    }
}

// ---------------- GEMM2: g_part[slot] = wgt * (g_h[slot] @ w2[e]) ----------------
__global__ void __launch_bounds__(128) k_gemm2(const float* w2) {
    const int e  = blockIdx.x;
    const int n0 = blockIdx.y * 128;
    const int ne = g_cnt[e];
    if (ne == 0) return;

    __shared__ float4             bs[2][KC][32];
    __shared__ unsigned long long as[2][KC][32];

    const int tid = threadIdx.x;
    const int ng  = tid & 31;
    const int mg  = tid >> 5;
    const int arl = tid & 31;
    const int aks = (tid >> 5) * 4;

    for (int m0 = 0; m0 < ne; m0 += 32) {
        unsigned long long acc[8][2];
        #pragma unroll
        for (int i = 0; i < 8; i++) { acc[i][0] = 0ULL; acc[i][1] = 0ULL; }

        const int ar = m0 + arl;
        const float* asrc = (ar < ne) ? (g_h + (size_t)g_slot[e * NTOK + ar] * NINT) : 0;

        {
            #pragma unroll
            for (int r = 0; r < 4; r++) {
                const int j  = tid + r * 128;
                const int kk = j >> 5, nn = j & 31;
                bs[0][kk][nn] = *(const float4*)(w2 + ((size_t)e * NINT + kk) * NHID + n0 + nn * 4);
            }
            float4 av = make_float4(0.f, 0.f, 0.f, 0.f);
            if (asrc) av = *(const float4*)(asrc + aks);
            as[0][aks + 0][arl] = pk2(av.x, av.x);
            as[0][aks + 1][arl] = pk2(av.y, av.y);
            as[0][aks + 2][arl] = pk2(av.z, av.z);
            as[0][aks + 3][arl] = pk2(av.w, av.w);
        }
        __syncthreads();

        const int nc = NINT / KC;
        for (int c = 0; c < nc; c++) {
            const int cur = c & 1;
            float4 pb0, pb1, pb2, pb3, pa;
            const bool more = (c + 1 < nc);
            if (more) {
                const int kn = (c + 1) * KC;
                {
                    int j = tid;             int kk = j >> 5, nn = j & 31;
                    pb0 = *(const float4*)(w2 + ((size_t)e * NINT + kn + kk) * NHID + n0 + nn * 4);
                }
                {
                    int j = tid + 128;       int kk = j >> 5, nn = j & 31;
                    pb1 = *(const float4*)(w2 + ((size_t)e * NINT + kn + kk) * NHID + n0 + nn * 4);
                }
                {
                    int j = tid + 256;       int kk = j >> 5, nn = j & 31;
                    pb2 = *(const float4*)(w2 + ((size_t)e * NINT + kn + kk) * NHID + n0 + nn * 4);
                }
                {
                    int j = tid + 384;       int kk = j >> 5, nn = j & 31;
                    pb3 = *(const float4*)(w2 + ((size_t)e * NINT + kn + kk) * NHID + n0 + nn * 4);
                }
                pa = make_float4(0.f, 0.f, 0.f, 0.f);
                if (asrc) pa = *(const float4*)(asrc + kn + aks);
            }

            #pragma unroll
            for (int k = 0; k < KC; k++) {
                const ulonglong2 b = *(const ulonglong2*)&bs[cur][k][ng];
                #pragma unroll
                for (int p = 0; p < 4; p++) {
                    const ulonglong2 a2 = *(const ulonglong2*)&as[cur][k][mg * 8 + p * 2];
                    ffma2(acc[p * 2    ][0], a2.x, b.x);
                    ffma2(acc[p * 2    ][1], a2.x, b.y);
                    ffma2(acc[p * 2 + 1][0], a2.y, b.x);
                    ffma2(acc[p * 2 + 1][1], a2.y, b.y);
                }
            }

            if (more) {
                const int nb = cur ^ 1;
                { int j = tid;       bs[nb][j >> 5][j & 31] = pb0; }
                { int j = tid + 128; bs[nb][j >> 5][j & 31] = pb1; }
                { int j = tid + 256; bs[nb][j >> 5][j & 31] = pb2; }
                { int j = tid + 384; bs[nb][j >> 5][j & 31] = pb3; }
                as[nb][aks + 0][arl] = pk2(pa.x, pa.x);
                as[nb][aks + 1][arl] = pk2(pa.y, pa.y);
                as[nb][aks + 2][arl] = pk2(pa.z, pa.z);
                as[nb][aks + 3][arl] = pk2(pa.w, pa.w);
            }
            __syncthreads();
        }

        #pragma unroll
        for (int i = 0; i < 8; i++) {
            const int row = m0 + mg * 8 + i;
            if (row < ne) {
                const int sl = g_slot[e * NTOK + row];
                const float sc = g_wgt[e * NTOK + row];
                float o0, o1, o2, o3;
                upk2(acc[i][0], o0, o1);
                upk2(acc[i][1], o2, o3);
                *(float4*)(g_part + (size_t)sl * NHID + n0 + ng * 4) =
                    make_float4(o0 * sc, o1 * sc, o2 * sc, o3 * sc);
            }
        }
    }
}

// ---------------- combine: out[t][h] = sum over 6 slots (float4) ----------------
__global__ void k_combine(float* out) {
    const int i = blockIdx.x * 256 + threadIdx.x;       // float4 index
    if (i >= NTOK * NHID / 4) return;
    const int t  = i / (NHID / 4);
    const int h4 = i - t * (NHID / 4);
    float4 s = make_float4(0.f, 0.f, 0.f, 0.f);
    for (int k = 0; k < KSEL; k++) {
        const float4 v = *(const float4*)(g_part + (size_t)(t * KSEL + k) * NHID + h4 * 4);
        s.x += v.x; s.y += v.y; s.z += v.z; s.w += v.w;
    }
    *(float4*)(out + (size_t)t * NHID + h4 * 4) = s;
}

// ---------------- launch ----------------
extern "C" void kernel_launch(void* const* d_in, const int* in_sizes, int n_in,
                              void* d_out, int out_size) {
    if (n_in < 4) return;

    // Ordinal binding, order- and unit-independent (sizes never interpreted
    // numerically): two largest = w1, w2 (original order on ties), then x, then gate_w.
    int used[16];
    for (int i = 0; i < 16; i++) used[i] = 0;
    const int m = (n_in < 16) ? n_in : 16;
    int ord[4];
    for (int r = 0; r < 4; r++) {
        int b = -1;
        for (int i = 0; i < m; i++)
            if (!used[i] && (b < 0 || (long long)in_sizes[i] > (long long)in_sizes[b])) b = i;
        if (b < 0) return;
        used[b] = 1;
        ord[r] = b;
    }
    const float* w1 = (const float*)d_in[ord[0]];
    const float* w2 = (const float*)d_in[ord[1]];
    const float* x  = (const float*)d_in[ord[2]];
    const float* gw = (const float*)d_in[ord[3]];
    float* out = (float*)d_out;

    k_router<<<NTOK, 256>>>(x, gw);
    k_build<<<NEXP, 256>>>();
    k_gemm1<<<dim3(NEXP, NINT / 128), 128>>>(w1, x);
    k_gemm2<<<dim3(NEXP, NHID / 128), 128>>>(w2);
    k_combine<<<(NTOK * NHID / 4 + 255) / 256, 256>>>(out);
}

// round 11
// speedup vs baseline: 1.7838x; 1.0008x over previous
#include <cuda_runtime.h>
#include <cstddef>

#define NTOK 256
#define NHID 2048
#define NEXP 64
#define NINT 1408
#define KSEL 6
#define KC   16

// ---------------- scratch (__device__ globals; no allocation) ----------------
__device__ int   g_cnt[NEXP];
__device__ int   g_tok[NEXP * NTOK];
__device__ int   g_slot[NEXP * NTOK];
__device__ float g_wgt[NEXP * NTOK];
__device__ int   g_tki[NTOK * KSEL];
__device__ float g_tkw[NTOK * KSEL];
__device__ __align__(16) float g_h[(size_t)NTOK * KSEL * NINT];
__device__ __align__(16) float g_part[(size_t)NTOK * KSEL * NHID];

// ---------------- packed f32x2 helpers ----------------
static __device__ __forceinline__ unsigned long long pk2(float lo, float hi) {
    unsigned long long r;
    asm("mov.b64 %0, {%1, %2};" : "=l"(r) : "f"(lo), "f"(hi));
    return r;
}
static __device__ __forceinline__ void upk2(unsigned long long v, float& lo, float& hi) {
    asm("mov.b64 {%0, %1}, %2;" : "=f"(lo), "=f"(hi) : "l"(v));
}
static __device__ __forceinline__ void ffma2(unsigned long long& d,
                                             unsigned long long a,
                                             unsigned long long b) {
    asm("fma.rn.f32x2 %0, %1, %2, %0;" : "+l"(d) : "l"(a), "l"(b));
}

// ---------------- router: one block per token, 256 threads ----------------
__global__ void k_router(const float* x, const float* gw) {
    __shared__ float xrow[NHID];
    __shared__ float part[4][NEXP];
    __shared__ float logits[NEXP];

    const int t = blockIdx.x;
    for (int i = threadIdx.x; i < NHID; i += 256) xrow[i] = x[(size_t)t * NHID + i];
    __syncthreads();

    const int e   = threadIdx.x & 63;
    const int seg = threadIdx.x >> 6;
    const int k0  = seg * 512;
    float a0 = 0.f, a1 = 0.f, a2 = 0.f, a3 = 0.f;
    for (int h = k0; h < k0 + 512; h += 4) {
        a0 += xrow[h + 0] * gw[(size_t)(h + 0) * NEXP + e];
        a1 += xrow[h + 1] * gw[(size_t)(h + 1) * NEXP + e];
        a2 += xrow[h + 2] * gw[(size_t)(h + 2) * NEXP + e];
        a3 += xrow[h + 3] * gw[(size_t)(h + 3) * NEXP + e];
    }
    part[seg][e] = (a0 + a1) + (a2 + a3);
    __syncthreads();
    if (threadIdx.x < NEXP)
        logits[threadIdx.x] = part[0][threadIdx.x] + part[1][threadIdx.x] +
                              part[2][threadIdx.x] + part[3][threadIdx.x];
    __syncthreads();

    if (threadIdx.x == 0) {
        // top-6 by logit (softmax monotone; denominator cancels in renorm).
        // Strict > keeps lowest index on ties (lax.top_k order).
        int   chosen[KSEL];
        float lval[KSEL];
        unsigned long long used = 0ULL;
        for (int k = 0; k < KSEL; k++) {
            float best = -1e30f; int bi = 0;
            for (int j = 0; j < NEXP; j++)
                if (((used >> j) & 1ULL) == 0ULL && logits[j] > best) { best = logits[j]; bi = j; }
            used |= (1ULL << bi);
            chosen[k] = bi;
            lval[k]   = best;
        }
        const float mx = lval[0];
        float w[KSEL], s = 0.0f;
        for (int k = 0; k < KSEL; k++) { w[k] = __expf(lval[k] - mx); s += w[k]; }
        const float inv = 1.0f / s;
        for (int k = 0; k < KSEL; k++) {
            g_tki[t * KSEL + k] = chosen[k];
            g_tkw[t * KSEL + k] = w[k] * inv;
        }
    }
}

// ---------------- parallel deterministic expert-list build ----------------
// Ballot + warp-prefix compaction over slot indices in ascending order:
// result order identical to the old serial scan.
__global__ void k_build() {
    const int e   = blockIdx.x;
    const int tid = threadIdx.x;
    __shared__ int wsum[8];
    __shared__ int base;
    if (tid == 0) base = 0;
    __syncthreads();

    for (int b0 = 0; b0 < NTOK * KSEL; b0 += 256) {
        const int idx = b0 + tid;                       // = t*KSEL + k, ascending
        const bool p  = (g_tki[idx] == e);
        const unsigned mask = __ballot_sync(0xffffffffu, p);
        const int lane = tid & 31;
        const int w    = tid >> 5;
        const int pre  = __popc(mask & ((1u << lane) - 1u));
        if (lane == 31) wsum[w] = __popc(mask);
        __syncthreads();
        int woff = 0;
        for (int j = 0; j < w; j++) woff += wsum[j];
        if (p) {
            const int pos = base + woff + pre;
            g_tok[e * NTOK + pos]  = idx / KSEL;
            g_slot[e * NTOK + pos] = idx;
            g_wgt[e * NTOK + pos]  = g_tkw[idx];
        }
        __syncthreads();
        if (tid == 0) {
            int tot = 0;
            for (int j = 0; j < 8; j++) tot += wsum[j];
            base += tot;
        }
        __syncthreads();
    }
    if (tid == 0) g_cnt[e] = base;
}

// ---------------- GEMM1: g_h[slot] = silu(x[tok] @ w1[e]) ----------------
// 128 threads, M-tile 32 (4 warps x 8 rows), N-tile 128 (32 lanes x 4 cols),
// KC=16 chunks, double-buffered smem, A duplicated as (a,a) pairs in [k][row].
__global__ void __launch_bounds__(128) k_gemm1(const float* w1, const float* x) {
    const int e  = blockIdx.x;
    const int n0 = blockIdx.y * 128;
    const int ne = g_cnt[e];
    if (ne == 0) return;

    __shared__ float4             bs[2][KC][32];   // B: [k][n/4]
    __shared__ unsigned long long as[2][KC][32];   // A dup: [k][row]

    const int tid = threadIdx.x;
    const int ng  = tid & 31;        // col group (4 cols)
    const int mg  = tid >> 5;        // 0..3 -> rows mg*8..mg*8+7
    const int arl = tid & 31;        // A staging row
    const int aks = (tid >> 5) * 4;  // A staging k offset (4 k's)

    for (int m0 = 0; m0 < ne; m0 += 32) {
        unsigned long long acc[8][2];
        #pragma unroll
        for (int i = 0; i < 8; i++) { acc[i][0] = 0ULL; acc[i][1] = 0ULL; }

        const int ar = m0 + arl;
        const float* asrc = (ar < ne) ? (x + (size_t)g_tok[e * NTOK + ar] * NHID) : 0;

        // prologue: stage chunk 0 into buffer 0
        {
            #pragma unroll
            for (int r = 0; r < 4; r++) {
                const int j  = tid + r * 128;
                const int kk = j >> 5, nn = j & 31;
                bs[0][kk][nn] = *(const float4*)(w1 + ((size_t)e * NHID + kk) * NINT + n0 + nn * 4);
            }
            float4 av = make_float4(0.f, 0.f, 0.f, 0.f);
            if (asrc) av = *(const float4*)(asrc + aks);
            as[0][aks + 0][arl] = pk2(av.x, av.x);
            as[0][aks + 1][arl] = pk2(av.y, av.y);
            as[0][aks + 2][arl] = pk2(av.z, av.z);
            as[0][aks + 3][arl] = pk2(av.w, av.w);
        }
        __syncthreads();

        const int nc = NHID / KC;
        for (int c = 0; c < nc; c++) {
            const int cur = c & 1;
            float4 pb0, pb1, pb2, pb3, pa;
            const bool more = (c + 1 < nc);
            if (more) {
                const int kn = (c + 1) * KC;
                {
                    int j = tid;             int kk = j >> 5, nn = j & 31;
                    pb0 = *(const float4*)(w1 + ((size_t)e * NHID + kn + kk) * NINT + n0 + nn * 4);
                }
                {
                    int j = tid + 128;       int kk = j >> 5, nn = j & 31;
                    pb1 = *(const float4*)(w1 + ((size_t)e * NHID + kn + kk) * NINT + n0 + nn * 4);
                }
                {
                    int j = tid + 256;       int kk = j >> 5, nn = j & 31;
                    pb2 = *(const float4*)(w1 + ((size_t)e * NHID + kn + kk) * NINT + n0 + nn * 4);
                }
                {
                    int j = tid + 384;       int kk = j >> 5, nn = j & 31;
                    pb3 = *(const float4*)(w1 + ((size_t)e * NHID + kn + kk) * NINT + n0 + nn * 4);
                }
                pa = make_float4(0.f, 0.f, 0.f, 0.f);
                if (asrc) pa = *(const float4*)(asrc + kn + aks);
            }

            #pragma unroll
            for (int k = 0; k < KC; k++) {
                const ulonglong2 b = *(const ulonglong2*)&bs[cur][k][ng];
                #pragma unroll
                for (int p = 0; p < 4; p++) {
                    const ulonglong2 a2 = *(const ulonglong2*)&as[cur][k][mg * 8 + p * 2];
                    ffma2(acc[p * 2    ][0], a2.x, b.x);
                    ffma2(acc[p * 2    ][1], a2.x, b.y);
                    ffma2(acc[p * 2 + 1][0], a2.y, b.x);
                    ffma2(acc[p * 2 + 1][1], a2.y, b.y);
                }
            }

            if (more) {
                const int nb = cur ^ 1;
                { int j = tid;       bs[nb][j >> 5][j & 31] = pb0; }
                { int j = tid + 128; bs[nb][j >> 5][j & 31] = pb1; }
                { int j = tid + 256; bs[nb][j >> 5][j & 31] = pb2; }
                { int j = tid + 384; bs[nb][j >> 5][j & 31] = pb3; }
                as[nb][aks + 0][arl] = pk2(pa.x, pa.x);
                as[nb][aks + 1][arl] = pk2(pa.y, pa.y);
                as[nb][aks + 2][arl] = pk2(pa.z, pa.z);
                as[nb][aks + 3][arl] = pk2(pa.w, pa.w);
            }
            __syncthreads();
        }

        #pragma unroll
        for (int i = 0; i < 8; i++) {
            const int row = m0 + mg * 8 + i;
            if (row < ne) {
                const int sl = g_slot[e * NTOK + row];
                float o0, o1, o2, o3;
                upk2(acc[i][0], o0, o1);
                upk2(acc[i][1], o2, o3);
                o0 = o0 / (1.0f + __expf(-o0));
                o1 = o1 / (1.0f + __expf(-o1));
                o2 = o2 / (1.0f + __expf(-o2));
                o3 = o3 / (1.0f + __expf(-o3));
                *(float4*)(g_h + (size_t)sl * NINT + n0 + ng * 4) = make_float4(o0, o1, o2, o3);
            }
        }
    }
}

// ---------------- GEMM2: g_part[slot] = wgt * (g_h[slot] @ w2[e]) ----------------
__global__ void __launch_bounds__(128) k_gemm2(const float* w2) {
    const int e  = blockIdx.x;
    const int n0 = blockIdx.y * 128;
    const int ne = g_cnt[e];
    if (ne == 0) return;

    __shared__ float4             bs[2][KC][32];
    __shared__ unsigned long long as[2][KC][32];

    const int tid = threadIdx.x;
    const int ng  = tid & 31;
    const int mg  = tid >> 5;
    const int arl = tid & 31;
    const int aks = (tid >> 5) * 4;

    for (int m0 = 0; m0 < ne; m0 += 32) {
        unsigned long long acc[8][2];
        #pragma unroll
        for (int i = 0; i < 8; i++) { acc[i][0] = 0ULL; acc[i][1] = 0ULL; }

        const int ar = m0 + arl;
        const float* asrc = (ar < ne) ? (g_h + (size_t)g_slot[e * NTOK + ar] * NINT) : 0;

        {
            #pragma unroll
            for (int r = 0; r < 4; r++) {
                const int j  = tid + r * 128;
                const int kk = j >> 5, nn = j & 31;
                bs[0][kk][nn] = *(const float4*)(w2 + ((size_t)e * NINT + kk) * NHID + n0 + nn * 4);
            }
            float4 av = make_float4(0.f, 0.f, 0.f, 0.f);
            if (asrc) av = *(const float4*)(asrc + aks);
            as[0][aks + 0][arl] = pk2(av.x, av.x);
            as[0][aks + 1][arl] = pk2(av.y, av.y);
            as[0][aks + 2][arl] = pk2(av.z, av.z);
            as[0][aks + 3][arl] = pk2(av.w, av.w);
        }
        __syncthreads();

        const int nc = NINT / KC;
        for (int c = 0; c < nc; c++) {
            const int cur = c & 1;
            float4 pb0, pb1, pb2, pb3, pa;
            const bool more = (c + 1 < nc);
            if (more) {
                const int kn = (c + 1) * KC;
                {
                    int j = tid;             int kk = j >> 5, nn = j & 31;
                    pb0 = *(const float4*)(w2 + ((size_t)e * NINT + kn + kk) * NHID + n0 + nn * 4);
                }
                {
                    int j = tid + 128;       int kk = j >> 5, nn = j & 31;
                    pb1 = *(const float4*)(w2 + ((size_t)e * NINT + kn + kk) * NHID + n0 + nn * 4);
                }
                {
                    int j = tid + 256;       int kk = j >> 5, nn = j & 31;
                    pb2 = *(const float4*)(w2 + ((size_t)e * NINT + kn + kk) * NHID + n0 + nn * 4);
                }
                {
                    int j = tid + 384;       int kk = j >> 5, nn = j & 31;
                    pb3 = *(const float4*)(w2 + ((size_t)e * NINT + kn + kk) * NHID + n0 + nn * 4);
                }
                pa = make_float4(0.f, 0.f, 0.f, 0.f);
                if (asrc) pa = *(const float4*)(asrc + kn + aks);
            }

            #pragma unroll
            for (int k = 0; k < KC; k++) {
                const ulonglong2 b = *(const ulonglong2*)&bs[cur][k][ng];
                #pragma unroll
                for (int p = 0; p < 4; p++) {
                    const ulonglong2 a2 = *(const ulonglong2*)&as[cur][k][mg * 8 + p * 2];
                    ffma2(acc[p * 2    ][0], a2.x, b.x);
                    ffma2(acc[p * 2    ][1], a2.x, b.y);
                    ffma2(acc[p * 2 + 1][0], a2.y, b.x);
                    ffma2(acc[p * 2 + 1][1], a2.y, b.y);
                }
            }

            if (more) {
                const int nb = cur ^ 1;
                { int j = tid;       bs[nb][j >> 5][j & 31] = pb0; }
                { int j = tid + 128; bs[nb][j >> 5][j & 31] = pb1; }
                { int j = tid + 256; bs[nb][j >> 5][j & 31] = pb2; }
                { int j = tid + 384; bs[nb][j >> 5][j & 31] = pb3; }
                as[nb][aks + 0][arl] = pk2(pa.x, pa.x);
                as[nb][aks + 1][arl] = pk2(pa.y, pa.y);
                as[nb][aks + 2][arl] = pk2(pa.z, pa.z);
                as[nb][aks + 3][arl] = pk2(pa.w, pa.w);
            }
            __syncthreads();
        }

        #pragma unroll
        for (int i = 0; i < 8; i++) {
            const int row = m0 + mg * 8 + i;
            if (row < ne) {
                const int sl = g_slot[e * NTOK + row];
                const float sc = g_wgt[e * NTOK + row];
                float o0, o1, o2, o3;
                upk2(acc[i][0], o0, o1);
                upk2(acc[i][1], o2, o3);
                *(float4*)(g_part + (size_t)sl * NHID + n0 + ng * 4) =
                    make_float4(o0 * sc, o1 * sc, o2 * sc, o3 * sc);
            }
        }
    }
}

// ---------------- combine: out[t][h] = sum over 6 slots (float4) ----------------
__global__ void k_combine(float* out) {
    const int i = blockIdx.x * 256 + threadIdx.x;       // float4 index
    if (i >= NTOK * NHID / 4) return;
    const int t  = i / (NHID / 4);
    const int h4 = i - t * (NHID / 4);
    float4 s = make_float4(0.f, 0.f, 0.f, 0.f);
    for (int k = 0; k < KSEL; k++) {
        const float4 v = *(const float4*)(g_part + (size_t)(t * KSEL + k) * NHID + h4 * 4);
        s.x += v.x; s.y += v.y; s.z += v.z; s.w += v.w;
    }
    *(float4*)(out + (size_t)t * NHID + h4 * 4) = s;
}

// ---------------- launch ----------------
extern "C" void kernel_launch(void* const* d_in, const int* in_sizes, int n_in,
                              void* d_out, int out_size) {
    if (n_in < 4) return;

    // Ordinal binding, order- and unit-independent (sizes never interpreted
    // numerically): two largest = w1, w2 (original order on ties), then x, then gate_w.
    int used[16];
    for (int i = 0; i < 16; i++) used[i] = 0;
    const int m = (n_in < 16) ? n_in : 16;
    int ord[4];
    for (int r = 0; r < 4; r++) {
        int b = -1;
        for (int i = 0; i < m; i++)
            if (!used[i] && (b < 0 || (long long)in_sizes[i] > (long long)in_sizes[b])) b = i;
        if (b < 0) return;
        used[b] = 1;
        ord[r] = b;
    }
    const float* w1 = (const float*)d_in[ord[0]];
    const float* w2 = (const float*)d_in[ord[1]];
    const float* x  = (const float*)d_in[ord[2]];
    const float* gw = (const float*)d_in[ord[3]];
    float* out = (float*)d_out;

    k_router<<<NTOK, 256>>>(x, gw);
    k_build<<<NEXP, 256>>>();
    k_gemm1<<<dim3(NEXP, NINT / 128), 128>>>(w1, x);
    k_gemm2<<<dim3(NEXP, NHID / 128), 128>>>(w2);
    k_combine<<<(NTOK * NHID / 4 + 255) / 256, 256>>>(out);
}